// round 8
// baseline (speedup 1.0000x reference)
#include <cuda_runtime.h>
#include <math.h>
#include <stdint.h>

#define B_ROWS 2048
#define D_DIM  512
#define C_CLS  32768
#define S_SCALE 64.0f
#define SQRT_S 8.0f
#define MARGIN  0.5f
#define EPS_CLIP 1e-7f

#define BM 128
#define BN 128
#define NCH 4                  // 512 / 128 (k128 bytes per chunk)
#define BUF_BYTES 32768        // A 16KB + B 16KB per stage
#define B_REGION  16384
#define N_TILES_M (B_ROWS / BM)   // 16
#define N_TILES_N (C_CLS / BN)    // 256
#define N_CTAS    (N_TILES_M * N_TILES_N)  // 4096

// ---------------------------------------------------------------------------
__device__ float  g_rowsum[B_ROWS];
__device__ float  g_tgt[B_ROWS];
__device__ __align__(16) uint8_t g_F8[B_ROWS * D_DIM];   // e4m3(8 * f_hat)
__device__ __align__(16) uint8_t g_W8[C_CLS * D_DIM];    // e4m3(8 * w_hat)
__device__ int g_wflag[N_TILES_N];   // 0=unclaimed 1=in-progress 2=ready
__device__ int g_fflag[N_TILES_M];
__device__ int g_done;

// fp8 e4m3 mma: D(16x8,f32) += A(16x32,e4m3) * B(8x32,e4m3)^T
__device__ __forceinline__ void mma_f8(float* c, const uint4& a,
                                       uint32_t b0, uint32_t b1) {
    asm volatile(
        "mma.sync.aligned.m16n8k32.row.col.f32.e4m3.e4m3.f32 "
        "{%0,%1,%2,%3}, {%4,%5,%6,%7}, {%8,%9}, {%0,%1,%2,%3};"
        : "+f"(c[0]), "+f"(c[1]), "+f"(c[2]), "+f"(c[3])
        : "r"(a.x), "r"(a.y), "r"(a.z), "r"(a.w), "r"(b0), "r"(b1));
}

__device__ __forceinline__ uint32_t pack_e4m3x2(float lo, float hi) {
    uint16_t r;
    asm("cvt.rn.satfinite.e4m3x2.f32 %0, %1, %2;" : "=h"(r) : "f"(hi), "f"(lo));
    return (uint32_t)r;
}
__device__ __forceinline__ uint32_t pack_e4m3x4(float a, float b, float c, float d) {
    return pack_e4m3x2(a, b) | (pack_e4m3x2(c, d) << 16);
}

__device__ __forceinline__ void spin_ready(int* f) {
    int v;
    do {
        asm volatile("ld.global.acquire.gpu.b32 %0, [%1];" : "=r"(v) : "l"(f));
        if (v != 2) __nanosleep(64);
    } while (v != 2);
}

// 256-thread cooperative tile prep: 128 rows -> e4m3(8 * row_hat)
__device__ void prep_tile(const float* __restrict__ src, uint8_t* __restrict__ dst,
                          int row0) {
    const int warp = threadIdx.x >> 5;
    const int lane = threadIdx.x & 31;
#pragma unroll 1
    for (int it = 0; it < 16; it++) {
        int row = row0 + warp * 16 + it;
        const float4* p = (const float4*)(src + (size_t)row * D_DIM);
        float4 v[4]; float ss = 0.0f;
#pragma unroll
        for (int i = 0; i < 4; i++) {
            v[i] = p[lane + 32 * i];
            ss = fmaf(v[i].x, v[i].x, fmaf(v[i].y, v[i].y, fmaf(v[i].z, v[i].z, fmaf(v[i].w, v[i].w, ss))));
        }
#pragma unroll
        for (int o = 16; o; o >>= 1) ss += __shfl_xor_sync(0xffffffffu, ss, o);
        float sc = SQRT_S / fmaxf(sqrtf(ss), 1e-12f);
        uint32_t* o32 = (uint32_t*)(dst + (size_t)row * D_DIM);
        o32[lane +  0] = pack_e4m3x4(v[0].x * sc, v[0].y * sc, v[0].z * sc, v[0].w * sc);
        o32[lane + 32] = pack_e4m3x4(v[1].x * sc, v[1].y * sc, v[1].z * sc, v[1].w * sc);
        o32[lane + 64] = pack_e4m3x4(v[2].x * sc, v[2].y * sc, v[2].z * sc, v[2].w * sc);
        o32[lane + 96] = pack_e4m3x4(v[3].x * sc, v[3].y * sc, v[3].z * sc, v[3].w * sc);
    }
}

// ---------------------------------------------------------------------------
// Kernel 1: zero rowsum/flags/counter + exact fp32 target cosine.
// grid = 256 blocks x 256 threads; block b: tgt rows b*8..b*8+7 (warp-per-row)
__global__ void init_tgt_kernel(const float* __restrict__ F,
                                const int* __restrict__ Y,
                                const float* __restrict__ W) {
    const int bid  = blockIdx.x;
    const int warp = threadIdx.x >> 5;
    const int lane = threadIdx.x & 31;

    if (threadIdx.x < 8) g_rowsum[bid * 8 + threadIdx.x] = 0.0f;
    if (threadIdx.x == 8) g_wflag[bid] = 0;
    if (threadIdx.x == 9 && bid < N_TILES_M) g_fflag[bid] = 0;
    if (threadIdx.x == 10 && bid == 0) g_done = 0;

    int row = bid * 8 + warp;
    int cls = Y[row];
    const float4* fp = (const float4*)(F + (size_t)row * D_DIM);
    const float4* wp = (const float4*)(W + (size_t)cls * D_DIM);
    float dot = 0.0f, ff = 0.0f, ww = 0.0f;
#pragma unroll
    for (int i = 0; i < 4; i++) {
        float4 a = fp[lane + 32 * i];
        float4 b = wp[lane + 32 * i];
        dot = fmaf(a.x, b.x, fmaf(a.y, b.y, fmaf(a.z, b.z, fmaf(a.w, b.w, dot))));
        ff  = fmaf(a.x, a.x, fmaf(a.y, a.y, fmaf(a.z, a.z, fmaf(a.w, a.w, ff))));
        ww  = fmaf(b.x, b.x, fmaf(b.y, b.y, fmaf(b.z, b.z, fmaf(b.w, b.w, ww))));
    }
#pragma unroll
    for (int o = 16; o; o >>= 1) {
        dot += __shfl_xor_sync(0xffffffffu, dot, o);
        ff  += __shfl_xor_sync(0xffffffffu, ff,  o);
        ww  += __shfl_xor_sync(0xffffffffu, ww,  o);
    }
    if (lane == 0)
        g_tgt[row] = dot / (fmaxf(sqrtf(ff), 1e-12f) * fmaxf(sqrtf(ww), 1e-12f));
}

// ---------------------------------------------------------------------------
// Kernel 2: claim-based prep + fp8 mma GEMM + exp-rowsum + fused loss tail.
__global__ void __launch_bounds__(256, 1)
gemm_exp_mma_kernel(const float* __restrict__ F,
                    const float* __restrict__ W,
                    float* __restrict__ out) {
    extern __shared__ __align__(16) char smb[];   // 2 * 32KB
    const int tid  = threadIdx.x;
    const int lane = tid & 31;
    const int warp = tid >> 5;
    const int wm = warp >> 2;          // 0..1
    const int wn = warp & 3;           // 0..3
    const int tn = blockIdx.x & (N_TILES_N - 1);   // wave-1 CTAs get distinct tn
    const int tm = blockIdx.x >> 8;

    // ---- claim-based on-demand tile prep ----
    __shared__ int sClaimF, sClaimW, sLast;
    if (tid == 0) {
        sClaimF = (atomicCAS(&g_fflag[tm], 0, 1) == 0);
        sClaimW = (atomicCAS(&g_wflag[tn], 0, 1) == 0);
    }
    __syncthreads();
    if (sClaimF) {
        prep_tile(F, g_F8, tm * BM);
        __syncthreads();
        __threadfence();
        if (tid == 0) atomicExch(&g_fflag[tm], 2);
    }
    if (sClaimW) {
        prep_tile(W, g_W8, tn * BN);
        __syncthreads();
        __threadfence();
        if (tid == 0) atomicExch(&g_wflag[tn], 2);
    }
    if (tid == 0) {
        if (!sClaimF) spin_ready(&g_fflag[tm]);
        if (!sClaimW) spin_ready(&g_wflag[tn]);
    }
    __syncthreads();

    // ---- loader setup: per thread 4 LDG.128 of A + 4 of B per k128 chunk ----
    const uint8_t* gA[4];
    const uint8_t* gB[4];
    uint32_t stA[4], stB[4];
#pragma unroll
    for (int i = 0; i < 4; i++) {
        int idx = tid + i * 256;
        int row = idx >> 3;             // 0..127
        int j   = idx & 7;              // 16-byte group in k128
        gA[i] = g_F8 + (size_t)(tm * BM + row) * D_DIM + j * 16;
        gB[i] = g_W8 + (size_t)(tn * BN + row) * D_DIM + j * 16;
        int ks  = j >> 1;
        int khi = j & 1;
        {
            int mm = row & 63, wmw = row >> 6, mt = mm >> 4, r = mm & 15;
            int r0 = r & 7, rbit = r >> 3;
            int L = r0 << 2;
            int phys = L ^ (((L >> 3) & 3) << 1) ^ (ks & 1);
            int region = (ks * 2 + wmw) * 4 + mt;
            stA[i] = (uint32_t)(region * 512 + phys * 16 + khi * 8 + rbit * 4);
        }
        {
            int nn = row & 31, wnw = row >> 5, nt = nn >> 3, g = nn & 7;
            int np = nt >> 1, nb = nt & 1;
            int L = g << 2;
            int phys = L ^ (((L >> 3) & 3) << 1) ^ (ks & 1);
            int region = (ks * 4 + wnw) * 2 + np;
            stB[i] = (uint32_t)(B_REGION + region * 512 + phys * 16 + nb * 8 + khi * 4);
        }
    }

    const int lxs = lane ^ (((lane >> 3) & 3) << 1);

    float acc[4][4][4];
#pragma unroll
    for (int a = 0; a < 4; a++)
#pragma unroll
        for (int b = 0; b < 4; b++)
#pragma unroll
            for (int c = 0; c < 4; c++) acc[a][b][c] = 0.0f;

    uint4 vA[4], vB[4];

    // prologue: chunk 0
#pragma unroll
    for (int i = 0; i < 4; i++) {
        vA[i] = *(const uint4*)(gA[i]);
        vB[i] = *(const uint4*)(gB[i]);
    }
    {
        char* buf = smb;
#pragma unroll
        for (int i = 0; i < 4; i++) {
            *(uint32_t*)(buf + (stA[i] ^ 0 )) = vA[i].x;
            *(uint32_t*)(buf + (stA[i] ^ 16)) = vA[i].y;
            *(uint32_t*)(buf + (stA[i] ^ 32)) = vA[i].z;
            *(uint32_t*)(buf + (stA[i] ^ 48)) = vA[i].w;
            *(uint32_t*)(buf + (stB[i] ^ 0 )) = vB[i].x;
            *(uint32_t*)(buf + (stB[i] ^ 16)) = vB[i].y;
            *(uint32_t*)(buf + (stB[i] ^ 32)) = vB[i].z;
            *(uint32_t*)(buf + (stB[i] ^ 48)) = vB[i].w;
        }
    }
    __syncthreads();

#pragma unroll 1
    for (int c = 0; c < NCH; c++) {
        if (c + 1 < NCH) {
            const int ko = (c + 1) * 128;
#pragma unroll
            for (int i = 0; i < 4; i++) {
                vA[i] = *(const uint4*)(gA[i] + ko);
                vB[i] = *(const uint4*)(gB[i] + ko);
            }
        }
        const char* buf = smb + (c & 1) * BUF_BYTES;
#pragma unroll
        for (int ks = 0; ks < 4; ks++) {
            const int lr = lxs ^ (ks & 1);
            uint4 afr[4], bfr[2];
#pragma unroll
            for (int mt = 0; mt < 4; mt++)
                afr[mt] = *(const uint4*)(buf + (((ks * 2 + wm) * 4 + mt) * 32 + lr) * 16);
#pragma unroll
            for (int np = 0; np < 2; np++)
                bfr[np] = *(const uint4*)(buf + B_REGION + (((ks * 4 + wn) * 2 + np) * 32 + lr) * 16);
#pragma unroll
            for (int mt = 0; mt < 4; mt++) {
                mma_f8(acc[mt][0], afr[mt], bfr[0].x, bfr[0].y);
                mma_f8(acc[mt][1], afr[mt], bfr[0].z, bfr[0].w);
                mma_f8(acc[mt][2], afr[mt], bfr[1].x, bfr[1].y);
                mma_f8(acc[mt][3], afr[mt], bfr[1].z, bfr[1].w);
            }
        }
        if (c + 1 < NCH) {
            char* nbuf = smb + ((c + 1) & 1) * BUF_BYTES;
#pragma unroll
            for (int i = 0; i < 4; i++) {
                *(uint32_t*)(nbuf + (stA[i] ^ 0 )) = vA[i].x;
                *(uint32_t*)(nbuf + (stA[i] ^ 16)) = vA[i].y;
                *(uint32_t*)(nbuf + (stA[i] ^ 32)) = vA[i].z;
                *(uint32_t*)(nbuf + (stA[i] ^ 48)) = vA[i].w;
                *(uint32_t*)(nbuf + (stB[i] ^ 0 )) = vB[i].x;
                *(uint32_t*)(nbuf + (stB[i] ^ 16)) = vB[i].y;
                *(uint32_t*)(nbuf + (stB[i] ^ 32)) = vB[i].z;
                *(uint32_t*)(nbuf + (stB[i] ^ 48)) = vB[i].w;
            }
        }
        __syncthreads();
    }

    // ---- epilogue: exp + row reduce + atomicAdd ----
    float s[4][2];
#pragma unroll
    for (int mt = 0; mt < 4; mt++) {
        float s0 = 0.0f, s1 = 0.0f;
#pragma unroll
        for (int nt = 0; nt < 4; nt++) {
            s0 += __expf(acc[mt][nt][0]) + __expf(acc[mt][nt][1]);
            s1 += __expf(acc[mt][nt][2]) + __expf(acc[mt][nt][3]);
        }
        s[mt][0] = s0; s[mt][1] = s1;
    }
#pragma unroll
    for (int o = 1; o < 4; o <<= 1)
#pragma unroll
        for (int mt = 0; mt < 4; mt++) {
            s[mt][0] += __shfl_xor_sync(0xffffffffu, s[mt][0], o);
            s[mt][1] += __shfl_xor_sync(0xffffffffu, s[mt][1], o);
        }
    if ((lane & 3) == 0) {
        int g = lane >> 2;
        int base = tm * BM + wm * 64 + g;
#pragma unroll
        for (int mt = 0; mt < 4; mt++) {
            atomicAdd(&g_rowsum[base + mt * 16],     s[mt][0]);
            atomicAdd(&g_rowsum[base + mt * 16 + 8], s[mt][1]);
        }
    }

    // ---- fused loss tail: last CTA reduces the loss ----
    __threadfence();
    if (tid == 0) sLast = (atomicAdd(&g_done, 1) == N_CTAS - 1);
    __syncthreads();
    if (sLast) {
        __shared__ double sh[256];
        double a = 0.0;
        for (int b = tid; b < B_ROWS; b += 256) {
            float t = fminf(fmaxf(g_tgt[b], -1.0f + EPS_CLIP), 1.0f - EPS_CLIP);
            float num = S_SCALE * cosf(acosf(t) + MARGIN);
            float excl = __ldcg(&g_rowsum[b]) - __expf(S_SCALE * t);
            double denom = (double)__expf(num) + (double)excl;
            a += (double)num - log(denom);
        }
        sh[tid] = a;
        __syncthreads();
        for (int st = 128; st > 0; st >>= 1) {
            if (tid < st) sh[tid] += sh[tid + st];
            __syncthreads();
        }
        if (tid == 0) out[0] = (float)(-sh[0] / (double)B_ROWS);
    }
}

// ---------------------------------------------------------------------------
extern "C" void kernel_launch(void* const* d_in, const int* in_sizes, int n_in,
                              void* d_out, int out_size) {
    const float* F = (const float*)d_in[0];
    const int*   Y = (const int*)d_in[1];
    const float* W = (const float*)d_in[2];
    float* out = (float*)d_out;

    cudaFuncSetAttribute(gemm_exp_mma_kernel,
                         cudaFuncAttributeMaxDynamicSharedMemorySize, 2 * BUF_BYTES);

    init_tgt_kernel<<<256, 256>>>(F, Y, W);
    gemm_exp_mma_kernel<<<N_CTAS, 256, 2 * BUF_BYTES>>>(F, W, out);
}

// round 9
// speedup vs baseline: 1.2366x; 1.2366x over previous
#include <cuda_runtime.h>
#include <math.h>
#include <stdint.h>

#define B_ROWS 2048
#define D_DIM  512
#define C_CLS  32768
#define S_SCALE 64.0f
#define SQRT_S 8.0f
#define MARGIN  0.5f
#define EPS_CLIP 1e-7f

#define BM 128
#define BN 128
#define NCH 4                  // 512 / 128 (k128 bytes per chunk)
#define BUF_BYTES 32768        // A 16KB + B 16KB per stage
#define B_REGION  16384
#define N_TILES_M (B_ROWS / BM)   // 16
#define N_TILES_N (C_CLS / BN)    // 256
#define N_CTAS    (N_TILES_M * N_TILES_N)  // 4096

// ---------------------------------------------------------------------------
__device__ float  g_rowsum[B_ROWS];
__device__ float  g_tgt[B_ROWS];
__device__ __align__(16) uint8_t g_F8[B_ROWS * D_DIM];   // e4m3(8 * f_hat)
__device__ __align__(16) uint8_t g_W8[C_CLS * D_DIM];    // e4m3(8 * w_hat)
__device__ int g_wflag[N_TILES_N];   // 0=unclaimed 1=in-progress 2=ready
__device__ int g_fflag[N_TILES_M];
__device__ int g_done;

// fp8 e4m3 mma: D(16x8,f32) += A(16x32,e4m3) * B(8x32,e4m3)^T
__device__ __forceinline__ void mma_f8(float* c, const uint4& a,
                                       uint32_t b0, uint32_t b1) {
    asm volatile(
        "mma.sync.aligned.m16n8k32.row.col.f32.e4m3.e4m3.f32 "
        "{%0,%1,%2,%3}, {%4,%5,%6,%7}, {%8,%9}, {%0,%1,%2,%3};"
        : "+f"(c[0]), "+f"(c[1]), "+f"(c[2]), "+f"(c[3])
        : "r"(a.x), "r"(a.y), "r"(a.z), "r"(a.w), "r"(b0), "r"(b1));
}

__device__ __forceinline__ uint32_t pack_e4m3x2(float lo, float hi) {
    uint16_t r;
    asm("cvt.rn.satfinite.e4m3x2.f32 %0, %1, %2;" : "=h"(r) : "f"(hi), "f"(lo));
    return (uint32_t)r;
}
__device__ __forceinline__ uint32_t pack_e4m3x4(float a, float b, float c, float d) {
    return pack_e4m3x2(a, b) | (pack_e4m3x2(c, d) << 16);
}

__device__ __forceinline__ void spin_ready(int* f) {
    int v;
    do {
        asm volatile("ld.global.acquire.gpu.b32 %0, [%1];" : "=r"(v) : "l"(f));
        if (v != 2) __nanosleep(64);
    } while (v != 2);
}

__device__ __forceinline__ float4 ldcs4(const float4* p) {
    float4 v;
    asm volatile("ld.global.cs.v4.f32 {%0,%1,%2,%3}, [%4];"
                 : "=f"(v.x), "=f"(v.y), "=f"(v.z), "=f"(v.w) : "l"(p));
    return v;
}

// 256-thread cooperative tile prep: 128 rows -> e4m3(8 * row_hat)
__device__ void prep_tile(const float* __restrict__ src, uint8_t* __restrict__ dst,
                          int row0) {
    const int warp = threadIdx.x >> 5;
    const int lane = threadIdx.x & 31;
#pragma unroll 1
    for (int it = 0; it < 16; it++) {
        int row = row0 + warp * 16 + it;
        const float4* p = (const float4*)(src + (size_t)row * D_DIM);
        float4 v[4]; float ss = 0.0f;
#pragma unroll
        for (int i = 0; i < 4; i++) {
            v[i] = ldcs4(p + lane + 32 * i);
            ss = fmaf(v[i].x, v[i].x, fmaf(v[i].y, v[i].y, fmaf(v[i].z, v[i].z, fmaf(v[i].w, v[i].w, ss))));
        }
#pragma unroll
        for (int o = 16; o; o >>= 1) ss += __shfl_xor_sync(0xffffffffu, ss, o);
        float sc = SQRT_S / fmaxf(sqrtf(ss), 1e-12f);
        uint32_t* o32 = (uint32_t*)(dst + (size_t)row * D_DIM);
        o32[lane +  0] = pack_e4m3x4(v[0].x * sc, v[0].y * sc, v[0].z * sc, v[0].w * sc);
        o32[lane + 32] = pack_e4m3x4(v[1].x * sc, v[1].y * sc, v[1].z * sc, v[1].w * sc);
        o32[lane + 64] = pack_e4m3x4(v[2].x * sc, v[2].y * sc, v[2].z * sc, v[2].w * sc);
        o32[lane + 96] = pack_e4m3x4(v[3].x * sc, v[3].y * sc, v[3].z * sc, v[3].w * sc);
    }
}

// ---------------------------------------------------------------------------
// Kernel 1: zero rowsum/flags/counter + exact fp32 target cosine.
__global__ void init_tgt_kernel(const float* __restrict__ F,
                                const int* __restrict__ Y,
                                const float* __restrict__ W) {
    const int bid  = blockIdx.x;
    const int warp = threadIdx.x >> 5;
    const int lane = threadIdx.x & 31;

    if (threadIdx.x < 8) g_rowsum[bid * 8 + threadIdx.x] = 0.0f;
    if (threadIdx.x == 8) g_wflag[bid] = 0;
    if (threadIdx.x == 9 && bid < N_TILES_M) g_fflag[bid] = 0;
    if (threadIdx.x == 10 && bid == 0) g_done = 0;

    int row = bid * 8 + warp;
    int cls = Y[row];
    const float4* fp = (const float4*)(F + (size_t)row * D_DIM);
    const float4* wp = (const float4*)(W + (size_t)cls * D_DIM);
    float dot = 0.0f, ff = 0.0f, ww = 0.0f;
#pragma unroll
    for (int i = 0; i < 4; i++) {
        float4 a = fp[lane + 32 * i];
        float4 b = wp[lane + 32 * i];
        dot = fmaf(a.x, b.x, fmaf(a.y, b.y, fmaf(a.z, b.z, fmaf(a.w, b.w, dot))));
        ff  = fmaf(a.x, a.x, fmaf(a.y, a.y, fmaf(a.z, a.z, fmaf(a.w, a.w, ff))));
        ww  = fmaf(b.x, b.x, fmaf(b.y, b.y, fmaf(b.z, b.z, fmaf(b.w, b.w, ww))));
    }
#pragma unroll
    for (int o = 16; o; o >>= 1) {
        dot += __shfl_xor_sync(0xffffffffu, dot, o);
        ff  += __shfl_xor_sync(0xffffffffu, ff,  o);
        ww  += __shfl_xor_sync(0xffffffffu, ww,  o);
    }
    if (lane == 0)
        g_tgt[row] = dot / (fmaxf(sqrtf(ff), 1e-12f) * fmaxf(sqrtf(ww), 1e-12f));
}

// ---------------------------------------------------------------------------
// Kernel 2: claim-based prep + fp8 mma GEMM + exp-rowsum + fused loss tail.
// __launch_bounds__(256, 2): cap regs at 128 so the mainloop keeps 2 CTAs/SM;
// cold prep/loss paths may spill, the hot loop must not.
__global__ void __launch_bounds__(256, 2)
gemm_exp_mma_kernel(const float* __restrict__ F,
                    const float* __restrict__ W,
                    float* __restrict__ out) {
    extern __shared__ __align__(16) char smb[];   // 2 * 32KB
    const int tid  = threadIdx.x;
    const int lane = tid & 31;
    const int warp = tid >> 5;
    const int wm = warp >> 2;          // 0..1
    const int wn = warp & 3;           // 0..3
    const int tn = blockIdx.x & (N_TILES_N - 1);   // wave-1 CTAs get distinct tn
    const int tm = blockIdx.x >> 8;

    // ---- claim-based on-demand tile prep ----
    __shared__ int sClaimF, sClaimW, sLast;
    if (tid == 0) {
        sClaimF = (atomicCAS(&g_fflag[tm], 0, 1) == 0);
        sClaimW = (atomicCAS(&g_wflag[tn], 0, 1) == 0);
    }
    __syncthreads();
    if (sClaimF) {
        prep_tile(F, g_F8, tm * BM);
        __syncthreads();
        __threadfence();
        if (tid == 0) atomicExch(&g_fflag[tm], 2);
    }
    if (sClaimW) {
        prep_tile(W, g_W8, tn * BN);
        __syncthreads();
        __threadfence();
        if (tid == 0) atomicExch(&g_wflag[tn], 2);
    }
    if (tid == 0) {
        if (!sClaimF) spin_ready(&g_fflag[tm]);
        if (!sClaimW) spin_ready(&g_wflag[tn]);
    }
    __syncthreads();

    // ---- loader setup: per thread 4 LDG.128 of A + 4 of B per k128 chunk ----
    const uint8_t* gA[4];
    const uint8_t* gB[4];
    uint32_t stA[4], stB[4];
#pragma unroll
    for (int i = 0; i < 4; i++) {
        int idx = tid + i * 256;
        int row = idx >> 3;             // 0..127
        int j   = idx & 7;              // 16-byte group in k128
        gA[i] = g_F8 + (size_t)(tm * BM + row) * D_DIM + j * 16;
        gB[i] = g_W8 + (size_t)(tn * BN + row) * D_DIM + j * 16;
        int ks  = j >> 1;
        int khi = j & 1;
        {
            int mm = row & 63, wmw = row >> 6, mt = mm >> 4, r = mm & 15;
            int r0 = r & 7, rbit = r >> 3;
            int L = r0 << 2;
            int phys = L ^ (((L >> 3) & 3) << 1) ^ (ks & 1);
            int region = (ks * 2 + wmw) * 4 + mt;
            stA[i] = (uint32_t)(region * 512 + phys * 16 + khi * 8 + rbit * 4);
        }
        {
            int nn = row & 31, wnw = row >> 5, nt = nn >> 3, g = nn & 7;
            int np = nt >> 1, nb = nt & 1;
            int L = g << 2;
            int phys = L ^ (((L >> 3) & 3) << 1) ^ (ks & 1);
            int region = (ks * 4 + wnw) * 2 + np;
            stB[i] = (uint32_t)(B_REGION + region * 512 + phys * 16 + nb * 8 + khi * 4);
        }
    }

    const int lxs = lane ^ (((lane >> 3) & 3) << 1);

    float acc[4][4][4];
#pragma unroll
    for (int a = 0; a < 4; a++)
#pragma unroll
        for (int b = 0; b < 4; b++)
#pragma unroll
            for (int c = 0; c < 4; c++) acc[a][b][c] = 0.0f;

    uint4 vA[4], vB[4];

    // prologue: chunk 0
#pragma unroll
    for (int i = 0; i < 4; i++) {
        vA[i] = *(const uint4*)(gA[i]);
        vB[i] = *(const uint4*)(gB[i]);
    }
    {
        char* buf = smb;
#pragma unroll
        for (int i = 0; i < 4; i++) {
            *(uint32_t*)(buf + (stA[i] ^ 0 )) = vA[i].x;
            *(uint32_t*)(buf + (stA[i] ^ 16)) = vA[i].y;
            *(uint32_t*)(buf + (stA[i] ^ 32)) = vA[i].z;
            *(uint32_t*)(buf + (stA[i] ^ 48)) = vA[i].w;
            *(uint32_t*)(buf + (stB[i] ^ 0 )) = vB[i].x;
            *(uint32_t*)(buf + (stB[i] ^ 16)) = vB[i].y;
            *(uint32_t*)(buf + (stB[i] ^ 32)) = vB[i].z;
            *(uint32_t*)(buf + (stB[i] ^ 48)) = vB[i].w;
        }
    }
    __syncthreads();

#pragma unroll 1
    for (int c = 0; c < NCH; c++) {
        if (c + 1 < NCH) {
            const int ko = (c + 1) * 128;
#pragma unroll
            for (int i = 0; i < 4; i++) {
                vA[i] = *(const uint4*)(gA[i] + ko);
                vB[i] = *(const uint4*)(gB[i] + ko);
            }
        }
        const char* buf = smb + (c & 1) * BUF_BYTES;
#pragma unroll
        for (int ks = 0; ks < 4; ks++) {
            const int lr = lxs ^ (ks & 1);
            uint4 afr[4], bfr[2];
#pragma unroll
            for (int mt = 0; mt < 4; mt++)
                afr[mt] = *(const uint4*)(buf + (((ks * 2 + wm) * 4 + mt) * 32 + lr) * 16);
#pragma unroll
            for (int np = 0; np < 2; np++)
                bfr[np] = *(const uint4*)(buf + B_REGION + (((ks * 4 + wn) * 2 + np) * 32 + lr) * 16);
#pragma unroll
            for (int mt = 0; mt < 4; mt++) {
                mma_f8(acc[mt][0], afr[mt], bfr[0].x, bfr[0].y);
                mma_f8(acc[mt][1], afr[mt], bfr[0].z, bfr[0].w);
                mma_f8(acc[mt][2], afr[mt], bfr[1].x, bfr[1].y);
                mma_f8(acc[mt][3], afr[mt], bfr[1].z, bfr[1].w);
            }
        }
        if (c + 1 < NCH) {
            char* nbuf = smb + ((c + 1) & 1) * BUF_BYTES;
#pragma unroll
            for (int i = 0; i < 4; i++) {
                *(uint32_t*)(nbuf + (stA[i] ^ 0 )) = vA[i].x;
                *(uint32_t*)(nbuf + (stA[i] ^ 16)) = vA[i].y;
                *(uint32_t*)(nbuf + (stA[i] ^ 32)) = vA[i].z;
                *(uint32_t*)(nbuf + (stA[i] ^ 48)) = vA[i].w;
                *(uint32_t*)(nbuf + (stB[i] ^ 0 )) = vB[i].x;
                *(uint32_t*)(nbuf + (stB[i] ^ 16)) = vB[i].y;
                *(uint32_t*)(nbuf + (stB[i] ^ 32)) = vB[i].z;
                *(uint32_t*)(nbuf + (stB[i] ^ 48)) = vB[i].w;
            }
        }
        __syncthreads();
    }

    // ---- epilogue: exp + row reduce + atomicAdd ----
    float s[4][2];
#pragma unroll
    for (int mt = 0; mt < 4; mt++) {
        float s0 = 0.0f, s1 = 0.0f;
#pragma unroll
        for (int nt = 0; nt < 4; nt++) {
            s0 += __expf(acc[mt][nt][0]) + __expf(acc[mt][nt][1]);
            s1 += __expf(acc[mt][nt][2]) + __expf(acc[mt][nt][3]);
        }
        s[mt][0] = s0; s[mt][1] = s1;
    }
#pragma unroll
    for (int o = 1; o < 4; o <<= 1)
#pragma unroll
        for (int mt = 0; mt < 4; mt++) {
            s[mt][0] += __shfl_xor_sync(0xffffffffu, s[mt][0], o);
            s[mt][1] += __shfl_xor_sync(0xffffffffu, s[mt][1], o);
        }
    if ((lane & 3) == 0) {
        int g = lane >> 2;
        int base = tm * BM + wm * 64 + g;
#pragma unroll
        for (int mt = 0; mt < 4; mt++) {
            atomicAdd(&g_rowsum[base + mt * 16],     s[mt][0]);
            atomicAdd(&g_rowsum[base + mt * 16 + 8], s[mt][1]);
        }
    }

    // ---- fused loss tail: last CTA reduces the loss ----
    __threadfence();
    if (tid == 0) sLast = (atomicAdd(&g_done, 1) == N_CTAS - 1);
    __syncthreads();
    if (sLast) {
        __shared__ double sh[256];
        double a = 0.0;
        for (int b = tid; b < B_ROWS; b += 256) {
            float t = fminf(fmaxf(g_tgt[b], -1.0f + EPS_CLIP), 1.0f - EPS_CLIP);
            float num = S_SCALE * cosf(acosf(t) + MARGIN);
            float excl = __ldcg(&g_rowsum[b]) - __expf(S_SCALE * t);
            double denom = (double)__expf(num) + (double)excl;
            a += (double)num - log(denom);
        }
        sh[tid] = a;
        __syncthreads();
        for (int st = 128; st > 0; st >>= 1) {
            if (tid < st) sh[tid] += sh[tid + st];
            __syncthreads();
        }
        if (tid == 0) out[0] = (float)(-sh[0] / (double)B_ROWS);
    }
}

// ---------------------------------------------------------------------------
extern "C" void kernel_launch(void* const* d_in, const int* in_sizes, int n_in,
                              void* d_out, int out_size) {
    const float* F = (const float*)d_in[0];
    const int*   Y = (const int*)d_in[1];
    const float* W = (const float*)d_in[2];
    float* out = (float*)d_out;

    cudaFuncSetAttribute(gemm_exp_mma_kernel,
                         cudaFuncAttributeMaxDynamicSharedMemorySize, 2 * BUF_BYTES);

    init_tgt_kernel<<<256, 256>>>(F, Y, W);
    gemm_exp_mma_kernel<<<N_CTAS, 256, 2 * BUF_BYTES>>>(F, W, out);
}

// round 10
// speedup vs baseline: 1.8515x; 1.4972x over previous
#include <cuda_runtime.h>
#include <math.h>
#include <stdint.h>

#define B_ROWS 2048
#define D_DIM  512
#define C_CLS  32768
#define S_SCALE 64.0f
#define SQRT_S 8.0f
#define MARGIN  0.5f
#define EPS_CLIP 1e-7f

#define BM 128
#define BN 128
#define NCH 4                  // 512 / 128 bytes per chunk
#define BUF_BYTES 32768        // A 16KB + B 16KB per stage
#define B_REGION  16384

// prep grid split (8 warps = 8 rows per block)
#define PREP_W_BLOCKS  (C_CLS / 8)             // 4096
#define PREP_F_BLOCKS  (B_ROWS / 8)            // 256
#define PREP_T_BLOCKS  (B_ROWS / 8)            // 256
#define PREP_BLOCKS    (PREP_W_BLOCKS + PREP_F_BLOCKS + PREP_T_BLOCKS)

// ---------------------------------------------------------------------------
__device__ float  g_rowsum[B_ROWS];
__device__ float  g_tgt[B_ROWS];
__device__ __align__(16) uint8_t g_F8[B_ROWS * D_DIM];   // e4m3(8 * f_hat)
__device__ __align__(16) uint8_t g_W8[C_CLS * D_DIM];    // e4m3(8 * w_hat)

// ---------------------------------------------------------------------------
__device__ __forceinline__ uint32_t smem_u32(const void* p) {
    uint32_t a;
    asm("{ .reg .u64 t; cvta.to.shared.u64 t, %1; cvt.u32.u64 %0, t; }" : "=r"(a) : "l"(p));
    return a;
}

__device__ __forceinline__ void mma_f8(float* c, const uint4& a,
                                       uint32_t b0, uint32_t b1) {
    asm volatile(
        "mma.sync.aligned.m16n8k32.row.col.f32.e4m3.e4m3.f32 "
        "{%0,%1,%2,%3}, {%4,%5,%6,%7}, {%8,%9}, {%0,%1,%2,%3};"
        : "+f"(c[0]), "+f"(c[1]), "+f"(c[2]), "+f"(c[3])
        : "r"(a.x), "r"(a.y), "r"(a.z), "r"(a.w), "r"(b0), "r"(b1));
}

__device__ __forceinline__ void ldsm4(uint4& d, uint32_t a) {
    asm volatile("ldmatrix.sync.aligned.m8n8.x4.shared.b16 {%0,%1,%2,%3}, [%4];"
                 : "=r"(d.x), "=r"(d.y), "=r"(d.z), "=r"(d.w) : "r"(a));
}

__device__ __forceinline__ void cpasync16(uint32_t dst, const void* src) {
    asm volatile("cp.async.cg.shared.global [%0], [%1], 16;" :: "r"(dst), "l"(src));
}
#define CP_COMMIT asm volatile("cp.async.commit_group;" ::: "memory")
#define CP_WAIT1  asm volatile("cp.async.wait_group 1;" ::: "memory")
#define CP_WAIT0  asm volatile("cp.async.wait_group 0;" ::: "memory")

__device__ __forceinline__ uint32_t pack_e4m3x2(float lo, float hi) {
    uint16_t r;
    asm("cvt.rn.satfinite.e4m3x2.f32 %0, %1, %2;" : "=h"(r) : "f"(hi), "f"(lo));
    return (uint32_t)r;
}
__device__ __forceinline__ uint32_t pack_e4m3x4(float a, float b, float c, float d) {
    return pack_e4m3x2(a, b) | (pack_e4m3x2(c, d) << 16);
}

// ---------------------------------------------------------------------------
// Fused prep (proven R7 form):
//   blocks [0, 4096)    : W rows -> g_W8 = e4m3(8 * w_hat)
//   blocks [4096, 4352) : F rows -> g_F8 = e4m3(8 * f_hat), zero g_rowsum
//   blocks [4352, 4608) : target cosine (exact fp32, self-contained)
__global__ void prep_kernel(const float* __restrict__ F,
                            const int* __restrict__ Y,
                            const float* __restrict__ W) {
    const int bid  = blockIdx.x;
    const int warp = threadIdx.x >> 5;
    const int lane = threadIdx.x & 31;

    if (bid < PREP_W_BLOCKS + PREP_F_BLOCKS) {
        const bool isW = bid < PREP_W_BLOCKS;
        int row = isW ? (bid * 8 + warp) : ((bid - PREP_W_BLOCKS) * 8 + warp);
        const float* src = isW ? W : F;
        if (!isW && lane == 0) g_rowsum[row] = 0.0f;
        const float4* p = (const float4*)(src + (size_t)row * D_DIM);
        float4 v[4]; float ss = 0.0f;
#pragma unroll
        for (int i = 0; i < 4; i++) {
            v[i] = p[lane + 32 * i];
            ss = fmaf(v[i].x, v[i].x, fmaf(v[i].y, v[i].y, fmaf(v[i].z, v[i].z, fmaf(v[i].w, v[i].w, ss))));
        }
#pragma unroll
        for (int o = 16; o; o >>= 1) ss += __shfl_xor_sync(0xffffffffu, ss, o);
        float sc = SQRT_S / fmaxf(sqrtf(ss), 1e-12f);
        uint8_t* dst = isW ? g_W8 : g_F8;
        uint32_t* o32 = (uint32_t*)(dst + (size_t)row * D_DIM);
        o32[lane +  0] = pack_e4m3x4(v[0].x * sc, v[0].y * sc, v[0].z * sc, v[0].w * sc);
        o32[lane + 32] = pack_e4m3x4(v[1].x * sc, v[1].y * sc, v[1].z * sc, v[1].w * sc);
        o32[lane + 64] = pack_e4m3x4(v[2].x * sc, v[2].y * sc, v[2].z * sc, v[2].w * sc);
        o32[lane + 96] = pack_e4m3x4(v[3].x * sc, v[3].y * sc, v[3].z * sc, v[3].w * sc);
    } else {
        int row = (bid - PREP_W_BLOCKS - PREP_F_BLOCKS) * 8 + warp;
        int cls = Y[row];
        const float4* fp = (const float4*)(F + (size_t)row * D_DIM);
        const float4* wp = (const float4*)(W + (size_t)cls * D_DIM);
        float dot = 0.0f, ff = 0.0f, ww = 0.0f;
#pragma unroll
        for (int i = 0; i < 4; i++) {
            float4 a = fp[lane + 32 * i];
            float4 b = wp[lane + 32 * i];
            dot = fmaf(a.x, b.x, fmaf(a.y, b.y, fmaf(a.z, b.z, fmaf(a.w, b.w, dot))));
            ff  = fmaf(a.x, a.x, fmaf(a.y, a.y, fmaf(a.z, a.z, fmaf(a.w, a.w, ff))));
            ww  = fmaf(b.x, b.x, fmaf(b.y, b.y, fmaf(b.z, b.z, fmaf(b.w, b.w, ww))));
        }
#pragma unroll
        for (int o = 16; o; o >>= 1) {
            dot += __shfl_xor_sync(0xffffffffu, dot, o);
            ff  += __shfl_xor_sync(0xffffffffu, ff,  o);
            ww  += __shfl_xor_sync(0xffffffffu, ww,  o);
        }
        if (lane == 0)
            g_tgt[row] = dot / (fmaxf(sqrtf(ff), 1e-12f) * fmaxf(sqrtf(ww), 1e-12f));
    }
}

// ---------------------------------------------------------------------------
// fp8 mma GEMM with cp.async staging + ldmatrix fragment loads.
// smem layout per buffer (32 KB): A tile 128 rows x 128B at +0, B at +16384.
// swizzle: 16B column j stored at j ^ (row & 7).
__global__ void __launch_bounds__(256, 2)
gemm_exp_mma_kernel() {
    extern __shared__ __align__(16) char smb[];   // 2 * 32KB
    const uint32_t smbase = smem_u32(smb);
    const int tid  = threadIdx.x;
    const int lane = tid & 31;
    const int warp = tid >> 5;
    const int wm = warp >> 2;          // 0..1
    const int wn = warp & 3;           // 0..3
    const int tm = blockIdx.y;
    const int tn = blockIdx.x;

    // ---- cp.async setup: per thread 4x16B of A + 4x16B of B per chunk ----
    const int jj = tid & 7;            // 16B column
    const int r0 = tid >> 3;           // base row 0..31 (rows r0 + 32i)
    const uint32_t dA = (uint32_t)(r0 * 128 + ((jj ^ (r0 & 7)) << 4));
    const uint32_t dB = dA + B_REGION;
    const uint8_t* sA = g_F8 + (size_t)(tm * BM + r0) * D_DIM + jj * 16;
    const uint8_t* sB = g_W8 + (size_t)(tn * BN + r0) * D_DIM + jj * 16;

    // ---- ldmatrix lane addressing ----
    const int l15 = lane & 15, xorl = lane & 7, hi = lane >> 4;
    uint32_t xk[4];
#pragma unroll
    for (int ks = 0; ks < 4; ks++)
        xk[ks] = (uint32_t)((((ks << 1) | hi) ^ xorl) << 4);
    const uint32_t aBase = smbase + ((wm * 64 + l15) << 7);
    const uint32_t bBase = smbase + B_REGION + ((wn * 32 + l15) << 7);

    float acc[4][4][4];
#pragma unroll
    for (int a = 0; a < 4; a++)
#pragma unroll
        for (int b = 0; b < 4; b++)
#pragma unroll
            for (int c = 0; c < 4; c++) acc[a][b][c] = 0.0f;

    // ---- prologue: prefetch chunks 0 and 1 ----
#pragma unroll
    for (int i = 0; i < 4; i++) {
        cpasync16(smbase + dA + i * 4096, sA + i * 16384);
        cpasync16(smbase + dB + i * 4096, sB + i * 16384);
    }
    CP_COMMIT;
#pragma unroll
    for (int i = 0; i < 4; i++) {
        cpasync16(smbase + BUF_BYTES + dA + i * 4096, sA + 128 + i * 16384);
        cpasync16(smbase + BUF_BYTES + dB + i * 4096, sB + 128 + i * 16384);
    }
    CP_COMMIT;

#pragma unroll
    for (int c = 0; c < NCH; c++) {
        if (c < NCH - 1) { CP_WAIT1; } else { CP_WAIT0; }
        __syncthreads();
        const uint32_t bo = (uint32_t)(c & 1) * BUF_BYTES;
#pragma unroll
        for (int ks = 0; ks < 4; ks++) {
            uint4 afr[4], b0, b1;
#pragma unroll
            for (int mt = 0; mt < 4; mt++)
                ldsm4(afr[mt], aBase + bo + (mt << 11) + xk[ks]);
            ldsm4(b0, bBase + bo + xk[ks]);
            ldsm4(b1, bBase + bo + (1 << 11) + xk[ks]);
#pragma unroll
            for (int mt = 0; mt < 4; mt++) {
                mma_f8(acc[mt][0], afr[mt], b0.x, b0.z);
                mma_f8(acc[mt][1], afr[mt], b0.y, b0.w);
                mma_f8(acc[mt][2], afr[mt], b1.x, b1.z);
                mma_f8(acc[mt][3], afr[mt], b1.y, b1.w);
            }
        }
        if (c + 2 < NCH) {
            __syncthreads();   // everyone done reading this buffer
            const uint8_t* pa = sA + (c + 2) * 128;
            const uint8_t* pb = sB + (c + 2) * 128;
#pragma unroll
            for (int i = 0; i < 4; i++) {
                cpasync16(smbase + bo + dA + i * 4096, pa + i * 16384);
                cpasync16(smbase + bo + dB + i * 4096, pb + i * 16384);
            }
            CP_COMMIT;
        }
    }

    // ---- epilogue: exp + row reduce + atomicAdd (unchanged mapping) ----
    float s[4][2];
#pragma unroll
    for (int mt = 0; mt < 4; mt++) {
        float s0 = 0.0f, s1 = 0.0f;
#pragma unroll
        for (int nt = 0; nt < 4; nt++) {
            s0 += __expf(acc[mt][nt][0]) + __expf(acc[mt][nt][1]);
            s1 += __expf(acc[mt][nt][2]) + __expf(acc[mt][nt][3]);
        }
        s[mt][0] = s0; s[mt][1] = s1;
    }
#pragma unroll
    for (int o = 1; o < 4; o <<= 1)
#pragma unroll
        for (int mt = 0; mt < 4; mt++) {
            s[mt][0] += __shfl_xor_sync(0xffffffffu, s[mt][0], o);
            s[mt][1] += __shfl_xor_sync(0xffffffffu, s[mt][1], o);
        }
    if ((lane & 3) == 0) {
        int g = lane >> 2;
        int base = tm * BM + wm * 64 + g;
#pragma unroll
        for (int mt = 0; mt < 4; mt++) {
            atomicAdd(&g_rowsum[base + mt * 16],     s[mt][0]);
            atomicAdd(&g_rowsum[base + mt * 16 + 8], s[mt][1]);
        }
    }
}

// ---------------------------------------------------------------------------
__global__ void loss_kernel(float* __restrict__ out) {
    __shared__ double sh[1024];
    double a = 0.0;
    for (int b = threadIdx.x; b < B_ROWS; b += blockDim.x) {
        float t = fminf(fmaxf(g_tgt[b], -1.0f + EPS_CLIP), 1.0f - EPS_CLIP);
        float num = S_SCALE * cosf(acosf(t) + MARGIN);
        float excl = g_rowsum[b] - __expf(S_SCALE * t);
        double denom = (double)__expf(num) + (double)excl;
        a += (double)num - log(denom);
    }
    sh[threadIdx.x] = a;
    __syncthreads();
    for (int s = 512; s > 0; s >>= 1) {
        if (threadIdx.x < s) sh[threadIdx.x] += sh[threadIdx.x + s];
        __syncthreads();
    }
    if (threadIdx.x == 0) out[0] = (float)(-sh[0] / (double)B_ROWS);
}

// ---------------------------------------------------------------------------
extern "C" void kernel_launch(void* const* d_in, const int* in_sizes, int n_in,
                              void* d_out, int out_size) {
    const float* F = (const float*)d_in[0];
    const int*   Y = (const int*)d_in[1];
    const float* W = (const float*)d_in[2];
    float* out = (float*)d_out;

    cudaFuncSetAttribute(gemm_exp_mma_kernel,
                         cudaFuncAttributeMaxDynamicSharedMemorySize, 2 * BUF_BYTES);

    prep_kernel<<<PREP_BLOCKS, 256>>>(F, Y, W);

    dim3 grid(C_CLS / BN, B_ROWS / BM);   // (256, 16)
    gemm_exp_mma_kernel<<<grid, 256, 2 * BUF_BYTES>>>();

    loss_kernel<<<1, 1024>>>(out);
}